// round 4
// baseline (speedup 1.0000x reference)
#include <cuda_runtime.h>

#define MN 50000      // nodes
#define KF 256        // in features
#define NF 128        // out features
#define NE 800000     // edges

// scratch
__device__ float g_support[(size_t)MN * NF];   // x @ W  (25.6 MB)
__device__ int   g_cnt[MN];                    // per-row edge counts
__device__ int   g_cur[MN];                    // running fill cursor
__device__ int   g_off[MN + 1];                // CSR row offsets
__device__ int   g_eid[NE];                    // edge ids grouped by row

// ---------------------------------------------------------------------------
// SGEMM: support[MN,NF] = x[MN,KF] @ w[KF,NF]
// 128x128 tile, BK=8, 256 threads, 8x8 per thread, double-buffered SMEM.
// ---------------------------------------------------------------------------
__global__ __launch_bounds__(256, 2) void gemm_kernel(const float* __restrict__ x,
                                                      const float* __restrict__ w) {
    __shared__ float As[2][8][128];   // [buf][k][m]
    __shared__ float Bs[2][8][128];   // [buf][k][n]

    const int tid = threadIdx.x;
    const int tx = tid & 15;          // n group
    const int ty = tid >> 4;          // m group
    const int blockRow = blockIdx.x * 128;

    const int aRow = tid >> 1;                       // 0..127
    const int aCol = (tid & 1) * 4;                  // 0 or 4
    const int aRowG = min(blockRow + aRow, MN - 1);  // clamp; store guarded below
    const int bRow = tid >> 5;                       // 0..7 (k)
    const int bCol = (tid & 31) * 4;                 // 0..124

    float acc[8][8];
    #pragma unroll
    for (int i = 0; i < 8; i++)
        #pragma unroll
        for (int j = 0; j < 8; j++) acc[i][j] = 0.0f;

    // prologue: load tile 0
    float4 av = *reinterpret_cast<const float4*>(&x[(size_t)aRowG * KF + aCol]);
    float4 bv = *reinterpret_cast<const float4*>(&w[(size_t)bRow * NF + bCol]);
    As[0][aCol + 0][aRow] = av.x;
    As[0][aCol + 1][aRow] = av.y;
    As[0][aCol + 2][aRow] = av.z;
    As[0][aCol + 3][aRow] = av.w;
    *reinterpret_cast<float4*>(&Bs[0][bRow][bCol]) = bv;
    __syncthreads();

    int buf = 0;
    for (int kt = 0; kt < KF; kt += 8) {
        const bool has_next = (kt + 8) < KF;
        if (has_next) {
            av = *reinterpret_cast<const float4*>(&x[(size_t)aRowG * KF + kt + 8 + aCol]);
            bv = *reinterpret_cast<const float4*>(&w[(size_t)(kt + 8 + bRow) * NF + bCol]);
        }

        #pragma unroll
        for (int k = 0; k < 8; k++) {
            float a[8], b[8];
            #pragma unroll
            for (int i = 0; i < 8; i++) a[i] = As[buf][k][ty * 8 + i];
            #pragma unroll
            for (int j = 0; j < 8; j++) b[j] = Bs[buf][k][tx * 8 + j];
            #pragma unroll
            for (int i = 0; i < 8; i++)
                #pragma unroll
                for (int j = 0; j < 8; j++)
                    acc[i][j] = fmaf(a[i], b[j], acc[i][j]);
        }

        if (has_next) {
            const int nb = buf ^ 1;
            As[nb][aCol + 0][aRow] = av.x;
            As[nb][aCol + 1][aRow] = av.y;
            As[nb][aCol + 2][aRow] = av.z;
            As[nb][aCol + 3][aRow] = av.w;
            *reinterpret_cast<float4*>(&Bs[nb][bRow][bCol]) = bv;
            __syncthreads();
            buf = nb;
        }
    }

    #pragma unroll
    for (int i = 0; i < 8; i++) {
        int row = blockRow + ty * 8 + i;
        if (row < MN) {
            float* dst = &g_support[(size_t)row * NF + tx * 8];
            *reinterpret_cast<float4*>(dst)     = make_float4(acc[i][0], acc[i][1], acc[i][2], acc[i][3]);
            *reinterpret_cast<float4*>(dst + 4) = make_float4(acc[i][4], acc[i][5], acc[i][6], acc[i][7]);
        }
    }
}

// ---------------------------------------------------------------------------
// CSR build
// ---------------------------------------------------------------------------
__global__ __launch_bounds__(256) void zero_cnt_kernel() {
    int i = blockIdx.x * 256 + threadIdx.x;
    if (i < MN) g_cnt[i] = 0;
}

__global__ __launch_bounds__(256) void hist_kernel(const int* __restrict__ rows) {
    int e = blockIdx.x * 256 + threadIdx.x;
    if (e < NE) atomicAdd(&g_cnt[rows[e]], 1);
}

// single-block exclusive scan over 50K counts (1024 threads, 49 each)
__global__ __launch_bounds__(1024) void scan_kernel() {
    __shared__ int part[1024];
    const int t = threadIdx.x;
    const int C = (MN + 1023) / 1024;   // 49
    const int base = t * C;

    int sum = 0;
    #pragma unroll 4
    for (int i = 0; i < C; i++) {
        int idx = base + i;
        if (idx < MN) sum += g_cnt[idx];
    }
    part[t] = sum;
    __syncthreads();

    // Hillis-Steele inclusive scan
    for (int off = 1; off < 1024; off <<= 1) {
        int v = (t >= off) ? part[t - off] : 0;
        __syncthreads();
        part[t] += v;
        __syncthreads();
    }

    int run = (t == 0) ? 0 : part[t - 1];  // exclusive prefix for this chunk
    for (int i = 0; i < C; i++) {
        int idx = base + i;
        if (idx < MN) {
            int c = g_cnt[idx];
            g_off[idx] = run;
            g_cur[idx] = run;
            run += c;
        }
    }
    if (t == 0) g_off[MN] = NE;
}

__global__ __launch_bounds__(256) void fill_kernel(const int* __restrict__ rows) {
    int e = blockIdx.x * 256 + threadIdx.x;
    if (e < NE) {
        int pos = atomicAdd(&g_cur[rows[e]], 1);
        g_eid[pos] = e;
    }
}

// ---------------------------------------------------------------------------
// Accumulate: one warp per output row. Lane handles 4 cols (float4).
// Gathers support rows (L2-resident), FMA in registers, fused ReLU + store.
// ---------------------------------------------------------------------------
__global__ __launch_bounds__(256) void acc_kernel(const float* __restrict__ vals,
                                                  const int* __restrict__ cols,
                                                  float* __restrict__ out) {
    const int r = blockIdx.x * 8 + (threadIdx.x >> 5);
    if (r >= MN) return;
    const int lane = threadIdx.x & 31;

    const int beg = g_off[r];
    const int end = g_off[r + 1];

    float4 acc = make_float4(0.f, 0.f, 0.f, 0.f);

    int i = beg;
    // unroll x2: two independent gather chains in flight
    for (; i + 1 < end; i += 2) {
        const int e0 = __ldg(&g_eid[i]);
        const int e1 = __ldg(&g_eid[i + 1]);
        const float v0 = __ldg(&vals[e0]);
        const float v1 = __ldg(&vals[e1]);
        const int c0 = __ldg(&cols[e0]);
        const int c1 = __ldg(&cols[e1]);
        const float4 s0 = __ldg(reinterpret_cast<const float4*>(g_support + (size_t)c0 * NF) + lane);
        const float4 s1 = __ldg(reinterpret_cast<const float4*>(g_support + (size_t)c1 * NF) + lane);
        acc.x = fmaf(v0, s0.x, acc.x);
        acc.y = fmaf(v0, s0.y, acc.y);
        acc.z = fmaf(v0, s0.z, acc.z);
        acc.w = fmaf(v0, s0.w, acc.w);
        acc.x = fmaf(v1, s1.x, acc.x);
        acc.y = fmaf(v1, s1.y, acc.y);
        acc.z = fmaf(v1, s1.z, acc.z);
        acc.w = fmaf(v1, s1.w, acc.w);
    }
    if (i < end) {
        const int e0 = __ldg(&g_eid[i]);
        const float v0 = __ldg(&vals[e0]);
        const int c0 = __ldg(&cols[e0]);
        const float4 s0 = __ldg(reinterpret_cast<const float4*>(g_support + (size_t)c0 * NF) + lane);
        acc.x = fmaf(v0, s0.x, acc.x);
        acc.y = fmaf(v0, s0.y, acc.y);
        acc.z = fmaf(v0, s0.z, acc.z);
        acc.w = fmaf(v0, s0.w, acc.w);
    }

    float4 o;
    o.x = fmaxf(acc.x, 0.f);
    o.y = fmaxf(acc.y, 0.f);
    o.z = fmaxf(acc.z, 0.f);
    o.w = fmaxf(acc.w, 0.f);
    *(reinterpret_cast<float4*>(out + (size_t)r * NF) + lane) = o;
}

extern "C" void kernel_launch(void* const* d_in, const int* in_sizes, int n_in,
                              void* d_out, int out_size) {
    const float* x    = (const float*)d_in[0];
    const float* w    = (const float*)d_in[1];
    const float* vals = (const float*)d_in[2];
    const int*   rows = (const int*)d_in[3];
    const int*   cols = (const int*)d_in[4];
    float* out = (float*)d_out;

    gemm_kernel<<<(MN + 127) / 128, 256>>>(x, w);

    zero_cnt_kernel<<<(MN + 255) / 256, 256>>>();
    hist_kernel<<<(NE + 255) / 256, 256>>>(rows);
    scan_kernel<<<1, 1024>>>();
    fill_kernel<<<(NE + 255) / 256, 256>>>(rows);

    acc_kernel<<<(MN + 7) / 8, 256>>>(vals, cols, out);
}

// round 5
// speedup vs baseline: 1.5738x; 1.5738x over previous
#include <cuda_runtime.h>

#define MN 50000      // nodes
#define KF 256        // in features
#define NF 128        // out features
#define NE 800000     // edges

#define NB_SCAN ((MN + 1023) / 1024)   // 49 scan blocks

// scratch
__device__ float g_support[(size_t)MN * NF];   // x @ W  (25.6 MB)
__device__ int   g_cnt[MN];                    // per-row edge counts
__device__ int   g_incl[MN];                   // within-block inclusive scan
__device__ int   g_bsum[64];                   // per-block sums
__device__ int   g_bpre[64];                   // exclusive prefix of block sums
__device__ int   g_cur[MN];                    // running fill cursor
__device__ int   g_off[MN + 1];                // CSR row offsets
__device__ int   g_eid[NE];                    // edge ids grouped by row

// ---------------------------------------------------------------------------
// SGEMM: support[MN,NF] = x[MN,KF] @ w[KF,NF]
// 128x128 tile, BK=8, 256 threads, 8x8 per thread, double-buffered SMEM.
// ---------------------------------------------------------------------------
__global__ __launch_bounds__(256, 2) void gemm_kernel(const float* __restrict__ x,
                                                      const float* __restrict__ w) {
    __shared__ float As[2][8][128];   // [buf][k][m]
    __shared__ float Bs[2][8][128];   // [buf][k][n]

    const int tid = threadIdx.x;
    const int tx = tid & 15;          // n group
    const int ty = tid >> 4;          // m group
    const int blockRow = blockIdx.x * 128;

    const int aRow = tid >> 1;                       // 0..127
    const int aCol = (tid & 1) * 4;                  // 0 or 4
    const int aRowG = min(blockRow + aRow, MN - 1);  // clamp; store guarded below
    const int bRow = tid >> 5;                       // 0..7 (k)
    const int bCol = (tid & 31) * 4;                 // 0..124

    float acc[8][8];
    #pragma unroll
    for (int i = 0; i < 8; i++)
        #pragma unroll
        for (int j = 0; j < 8; j++) acc[i][j] = 0.0f;

    // prologue: load tile 0
    float4 av = *reinterpret_cast<const float4*>(&x[(size_t)aRowG * KF + aCol]);
    float4 bv = *reinterpret_cast<const float4*>(&w[(size_t)bRow * NF + bCol]);
    As[0][aCol + 0][aRow] = av.x;
    As[0][aCol + 1][aRow] = av.y;
    As[0][aCol + 2][aRow] = av.z;
    As[0][aCol + 3][aRow] = av.w;
    *reinterpret_cast<float4*>(&Bs[0][bRow][bCol]) = bv;
    __syncthreads();

    int buf = 0;
    for (int kt = 0; kt < KF; kt += 8) {
        const bool has_next = (kt + 8) < KF;
        if (has_next) {
            av = *reinterpret_cast<const float4*>(&x[(size_t)aRowG * KF + kt + 8 + aCol]);
            bv = *reinterpret_cast<const float4*>(&w[(size_t)(kt + 8 + bRow) * NF + bCol]);
        }

        #pragma unroll
        for (int k = 0; k < 8; k++) {
            float a[8], b[8];
            #pragma unroll
            for (int i = 0; i < 8; i++) a[i] = As[buf][k][ty * 8 + i];
            #pragma unroll
            for (int j = 0; j < 8; j++) b[j] = Bs[buf][k][tx * 8 + j];
            #pragma unroll
            for (int i = 0; i < 8; i++)
                #pragma unroll
                for (int j = 0; j < 8; j++)
                    acc[i][j] = fmaf(a[i], b[j], acc[i][j]);
        }

        if (has_next) {
            const int nb = buf ^ 1;
            As[nb][aCol + 0][aRow] = av.x;
            As[nb][aCol + 1][aRow] = av.y;
            As[nb][aCol + 2][aRow] = av.z;
            As[nb][aCol + 3][aRow] = av.w;
            *reinterpret_cast<float4*>(&Bs[nb][bRow][bCol]) = bv;
            __syncthreads();
            buf = nb;
        }
    }

    #pragma unroll
    for (int i = 0; i < 8; i++) {
        int row = blockRow + ty * 8 + i;
        if (row < MN) {
            float* dst = &g_support[(size_t)row * NF + tx * 8];
            *reinterpret_cast<float4*>(dst)     = make_float4(acc[i][0], acc[i][1], acc[i][2], acc[i][3]);
            *reinterpret_cast<float4*>(dst + 4) = make_float4(acc[i][4], acc[i][5], acc[i][6], acc[i][7]);
        }
    }
}

// ---------------------------------------------------------------------------
// CSR build
// ---------------------------------------------------------------------------
__global__ __launch_bounds__(256) void zero_cnt_kernel() {
    int i = blockIdx.x * 256 + threadIdx.x;
    if (i < MN) g_cnt[i] = 0;
}

__global__ __launch_bounds__(256) void hist_kernel(const int* __restrict__ rows) {
    int e = blockIdx.x * 256 + threadIdx.x;
    if (e < NE) atomicAdd(&g_cnt[rows[e]], 1);
}

// Phase A: per-block inclusive scan of 1024 counts (coalesced)
__global__ __launch_bounds__(1024) void scanA_kernel() {
    __shared__ int sm[1024];
    const int t = threadIdx.x;
    const int i = blockIdx.x * 1024 + t;
    const int v = (i < MN) ? g_cnt[i] : 0;
    sm[t] = v;
    __syncthreads();
    #pragma unroll
    for (int off = 1; off < 1024; off <<= 1) {
        int u = (t >= off) ? sm[t - off] : 0;
        __syncthreads();
        sm[t] += u;
        __syncthreads();
    }
    if (i < MN) g_incl[i] = sm[t];
    if (t == 1023) g_bsum[blockIdx.x] = sm[1023];
}

// Phase B: scan the 49 block sums (1 block, 64 threads)
__global__ __launch_bounds__(64) void scanB_kernel() {
    __shared__ int sm[64];
    const int t = threadIdx.x;
    const int v = (t < NB_SCAN) ? g_bsum[t] : 0;
    sm[t] = v;
    __syncthreads();
    #pragma unroll
    for (int off = 1; off < 64; off <<= 1) {
        int u = (t >= off) ? sm[t - off] : 0;
        __syncthreads();
        sm[t] += u;
        __syncthreads();
    }
    g_bpre[t] = sm[t] - v;   // exclusive prefix
}

// Phase C: write exclusive offsets + cursors
__global__ __launch_bounds__(1024) void scanC_kernel() {
    const int i = blockIdx.x * 1024 + threadIdx.x;
    if (i < MN) {
        const int off = g_incl[i] - g_cnt[i] + g_bpre[blockIdx.x];
        g_off[i] = off;
        g_cur[i] = off;
    }
    if (i == 0) g_off[MN] = NE;
}

__global__ __launch_bounds__(256) void fill_kernel(const int* __restrict__ rows) {
    int e = blockIdx.x * 256 + threadIdx.x;
    if (e < NE) {
        int pos = atomicAdd(&g_cur[rows[e]], 1);
        g_eid[pos] = e;
    }
}

// ---------------------------------------------------------------------------
// Accumulate: one warp per output row. Lane handles 4 cols (float4).
// ---------------------------------------------------------------------------
__global__ __launch_bounds__(256) void acc_kernel(const float* __restrict__ vals,
                                                  const int* __restrict__ cols,
                                                  float* __restrict__ out) {
    const int r = blockIdx.x * 8 + (threadIdx.x >> 5);
    if (r >= MN) return;
    const int lane = threadIdx.x & 31;

    const int beg = g_off[r];
    const int end = g_off[r + 1];

    float4 acc = make_float4(0.f, 0.f, 0.f, 0.f);

    int i = beg;
    for (; i + 1 < end; i += 2) {
        const int e0 = __ldg(&g_eid[i]);
        const int e1 = __ldg(&g_eid[i + 1]);
        const float v0 = __ldg(&vals[e0]);
        const float v1 = __ldg(&vals[e1]);
        const int c0 = __ldg(&cols[e0]);
        const int c1 = __ldg(&cols[e1]);
        const float4 s0 = __ldg(reinterpret_cast<const float4*>(g_support + (size_t)c0 * NF) + lane);
        const float4 s1 = __ldg(reinterpret_cast<const float4*>(g_support + (size_t)c1 * NF) + lane);
        acc.x = fmaf(v0, s0.x, acc.x);
        acc.y = fmaf(v0, s0.y, acc.y);
        acc.z = fmaf(v0, s0.z, acc.z);
        acc.w = fmaf(v0, s0.w, acc.w);
        acc.x = fmaf(v1, s1.x, acc.x);
        acc.y = fmaf(v1, s1.y, acc.y);
        acc.z = fmaf(v1, s1.z, acc.z);
        acc.w = fmaf(v1, s1.w, acc.w);
    }
    if (i < end) {
        const int e0 = __ldg(&g_eid[i]);
        const float v0 = __ldg(&vals[e0]);
        const int c0 = __ldg(&cols[e0]);
        const float4 s0 = __ldg(reinterpret_cast<const float4*>(g_support + (size_t)c0 * NF) + lane);
        acc.x = fmaf(v0, s0.x, acc.x);
        acc.y = fmaf(v0, s0.y, acc.y);
        acc.z = fmaf(v0, s0.z, acc.z);
        acc.w = fmaf(v0, s0.w, acc.w);
    }

    float4 o;
    o.x = fmaxf(acc.x, 0.f);
    o.y = fmaxf(acc.y, 0.f);
    o.z = fmaxf(acc.z, 0.f);
    o.w = fmaxf(acc.w, 0.f);
    *(reinterpret_cast<float4*>(out + (size_t)r * NF) + lane) = o;
}

// ---------------------------------------------------------------------------
// Launch: fork CSR build onto a side stream so it overlaps the GEMM.
// Stream/events are created once, on the (uncaptured) first call.
// ---------------------------------------------------------------------------
static cudaStream_t s_side = nullptr;
static cudaEvent_t  s_evFork = nullptr;
static cudaEvent_t  s_evJoin = nullptr;

extern "C" void kernel_launch(void* const* d_in, const int* in_sizes, int n_in,
                              void* d_out, int out_size) {
    const float* x    = (const float*)d_in[0];
    const float* w    = (const float*)d_in[1];
    const float* vals = (const float*)d_in[2];
    const int*   rows = (const int*)d_in[3];
    const int*   cols = (const int*)d_in[4];
    float* out = (float*)d_out;

    if (!s_side) {
        cudaStreamCreateWithFlags(&s_side, cudaStreamNonBlocking);
        cudaEventCreateWithFlags(&s_evFork, cudaEventDisableTiming);
        cudaEventCreateWithFlags(&s_evJoin, cudaEventDisableTiming);
    }

    // fork: CSR build on side stream
    cudaEventRecord(s_evFork, 0);
    cudaStreamWaitEvent(s_side, s_evFork, 0);

    zero_cnt_kernel<<<(MN + 255) / 256, 256, 0, s_side>>>();
    hist_kernel<<<(NE + 255) / 256, 256, 0, s_side>>>(rows);
    scanA_kernel<<<NB_SCAN, 1024, 0, s_side>>>();
    scanB_kernel<<<1, 64, 0, s_side>>>();
    scanC_kernel<<<NB_SCAN, 1024, 0, s_side>>>();
    fill_kernel<<<(NE + 255) / 256, 256, 0, s_side>>>(rows);
    cudaEventRecord(s_evJoin, s_side);

    // main stream: GEMM (independent of CSR build)
    gemm_kernel<<<(MN + 127) / 128, 256>>>(x, w);

    // join, then accumulate
    cudaStreamWaitEvent(0, s_evJoin, 0);
    acc_kernel<<<(MN + 7) / 8, 256>>>(vals, cols, out);
}